// round 2
// baseline (speedup 1.0000x reference)
#include <cuda_runtime.h>
#include <cuda_bf16.h>

#define HW 256
#define NT 256
#define TILE 8
#define SP 9                 // padded float4 row stride (horizontal layout)
#define PLANE (HW * HW)

// Per-direction scratch: 4 dirs x 128 planes x 256x256 fp32 = 134 MB.
__device__ float g_scratch[512 * PLANE];

__global__ __launch_bounds__(NT) void spn_scan(
    const float* __restrict__ x,
    const float* __restrict__ mask)
{
    extern __shared__ float4 sq[];                 // packed {p,a,b,c}: HW*SP float4
    float* so = (float*)(sq + HW * SP);            // horizontal output staging (HW*SP floats)
    float* hb = so + HW * SP;                      // h ring: 2 x (HW+2), zero-padded

    const int k   = threadIdx.x;
    const int blk = blockIdx.x;
    const int dir = blk >> 7;                      // 0:h-fwd 1:h-rev 2:v-fwd 3:v-rev
    const int bc  = blk & 127;
    const int b   = bc >> 5;
    const int c   = bc & 31;
    const bool horiz = (dir < 2);
    const bool rev   = (dir & 1);

    const float* mb  = mask + (size_t)bc * PLANE;
    const float* g1b = x + (size_t)(b * 384 + (3 * dir + 0) * 32 + c) * PLANE;
    const float* g2b = x + (size_t)(b * 384 + (3 * dir + 1) * 32 + c) * PLANE;
    const float* g3b = x + (size_t)(b * 384 + (3 * dir + 2) * 32 + c) * PLANE;
    float* scr = g_scratch + (size_t)blk * PLANE;

    for (int i = k; i < 2 * (HW + 2); i += NT) hb[i] = 0.f;
    float* cur = hb;
    float* nxt = hb + (HW + 2);
    float hreg = 0.f;

    // ---- prefetch tile 0 into registers (float4, coalesced 32B sectors) ----
    float4 rm[2], r1[2], r2[2], r3[2];
    {
        int base0 = rev ? (HW - TILE) : 0;
        #pragma unroll
        for (int hf = 0; hf < 2; ++hf) {
            int i = (k + hf * NT) * 4;             // flat element index in tile
            int g = horiz ? ((i >> 3) * HW + base0 + (i & 7)) : (base0 * HW + i);
            rm[hf] = *(const float4*)(mb  + g);
            r1[hf] = *(const float4*)(g1b + g);
            r2[hf] = *(const float4*)(g2b + g);
            r3[hf] = *(const float4*)(g3b + g);
        }
    }
    __syncthreads();                               // hb zeros visible

    for (int t = 0; t < HW / TILE; ++t) {
        const int base0 = rev ? (HW - TILE - TILE * t) : (TILE * t);

        // ---- normalize tile t from regs, pack into smem float4 {p,a,b,c} ----
        #pragma unroll
        for (int hf = 0; hf < 2; ++hf) {
            int i = (k + hf * NT) * 4;
            const float* Rm = (const float*)&rm[hf];
            const float* R1 = (const float*)&r1[hf];
            const float* R2 = (const float*)&r2[hf];
            const float* R3 = (const float*)&r3[hf];
            #pragma unroll
            for (int e = 0; e < 4; ++e) {
                float G1 = R1[e], G2 = R2[e], G3 = R3[e];
                float s = fabsf(G1) + fabsf(G2) + fabsf(G3) + 1e-7f;
                float r = (s >= 1.f) ? __fdividef(1.f, s) : 1.f;
                float a = G1 * r, bb = G2 * r, cc = G3 * r;
                float p = (1.f - a - bb - cc) * Rm[e];
                int ii = i + e;
                int sidx = horiz ? ((ii >> 3) * SP + (ii & 7)) : ii;
                sq[sidx] = make_float4(p, a, bb, cc);
            }
        }

        // ---- flush previous horizontal staging tile (coalesced STG.128) ----
        if (horiz && t > 0) {
            int pb = rev ? (HW - TILE * t) : (TILE * (t - 1));
            #pragma unroll
            for (int hf = 0; hf < 2; ++hf) {
                int i = (k + hf * NT) * 4;
                int row = i >> 3, col = i & 7;
                float* s = so + row * SP + col;
                float4 v = make_float4(s[0], s[1], s[2], s[3]);
                *(float4*)(scr + row * HW + pb + col) = v;
            }
        }
        __syncthreads();                           // sq visible; so reads done

        // ---- issue prefetch for tile t+1 (drains under the scan below) ----
        if (t + 1 < HW / TILE) {
            int nb = rev ? (HW - TILE - TILE * (t + 1)) : (TILE * (t + 1));
            #pragma unroll
            for (int hf = 0; hf < 2; ++hf) {
                int i = (k + hf * NT) * 4;
                int g = horiz ? ((i >> 3) * HW + nb + (i & 7)) : (nb * HW + i);
                rm[hf] = *(const float4*)(mb  + g);
                r1[hf] = *(const float4*)(g1b + g);
                r2[hf] = *(const float4*)(g2b + g);
                r3[hf] = *(const float4*)(g3b + g);
            }
        }

        // ---- 8 sequential scan steps (1 LDS.128 + 1 STS each) ----
        #pragma unroll
        for (int st = 0; st < TILE; ++st) {
            int L = rev ? (TILE - 1 - st) : st;
            float4 q = sq[horiz ? (k * SP + L) : (L * HW + k)];
            float hm = cur[k];                     // h_prev(k-1), pad -> 0
            float hp = cur[k + 2];                 // h_prev(k+1), pad -> 0
            float hn = fmaf(q.y, hm, q.x);
            hn = fmaf(q.z, hreg, hn);
            hn = fmaf(q.w, hp, hn);
            hreg = hn;
            nxt[k + 1] = hn;
            if (horiz) so[k * SP + L] = hn;
            else       scr[(base0 + L) * HW + k] = hn;   // coalesced STG.32
            __syncthreads();
            float* tmp = cur; cur = nxt; nxt = tmp;
        }
    }

    // ---- final horizontal flush ----
    if (horiz) {
        int pb = rev ? 0 : (HW - TILE);
        #pragma unroll
        for (int hf = 0; hf < 2; ++hf) {
            int i = (k + hf * NT) * 4;
            int row = i >> 3, col = i & 7;
            float* s = so + row * SP + col;
            float4 v = make_float4(s[0], s[1], s[2], s[3]);
            *(float4*)(scr + row * HW + pb + col) = v;
        }
    }
}

// out[i] = max over 4 directions of scratch — pure streaming, float4.
__global__ __launch_bounds__(NT) void spn_max(float* __restrict__ out, int n4)
{
    int i = blockIdx.x * NT + threadIdx.x;
    if (i >= n4) return;
    const int off = 128 * PLANE / 4;
    const float4* s = (const float4*)g_scratch;
    float4 a = s[i], b = s[i + off], c = s[i + 2 * off], d = s[i + 3 * off];
    float4 r;
    r.x = fmaxf(fmaxf(a.x, b.x), fmaxf(c.x, d.x));
    r.y = fmaxf(fmaxf(a.y, b.y), fmaxf(c.y, d.y));
    r.z = fmaxf(fmaxf(a.z, b.z), fmaxf(c.z, d.z));
    r.w = fmaxf(fmaxf(a.w, b.w), fmaxf(c.w, d.w));
    ((float4*)out)[i] = r;
}

extern "C" void kernel_launch(void* const* d_in, const int* in_sizes, int n_in,
                              void* d_out, int out_size) {
    const float* x    = (const float*)d_in[0];
    const float* mask = (const float*)d_in[1];
    if (n_in >= 2 && in_sizes[0] < in_sizes[1]) {   // defensive: x is 12x mask
        x    = (const float*)d_in[1];
        mask = (const float*)d_in[0];
    }
    size_t smem = (size_t)(HW * SP * 16 + HW * SP * 4 + 2 * (HW + 2) * 4); // 48,144 B
    spn_scan<<<512, NT, smem>>>(x, mask);
    int n4 = out_size / 4;                          // 2,097,152 float4
    spn_max<<<(n4 + NT - 1) / NT, NT>>>((float*)d_out, n4);
}

// round 3
// speedup vs baseline: 1.0638x; 1.0638x over previous
#include <cuda_runtime.h>
#include <cuda_bf16.h>

#define HW 256
#define PLANE (HW * HW)
#define TILE 8
#define NT 256
#define SQS 289              // smem gate row stride in float4 units (bank-conflict-free)
#define OSS 66               // out-staging row stride in float4 units

// Per-(plane,dir) scratch: 512 planes x 256KB = 134 MB.
// dirs 0,1 (horizontal) stored TRANSPOSED [w][h]; dirs 2,3 natural [h][w].
__device__ float g_scratch[512 * PLANE];

__global__ __launch_bounds__(NT) void spn_scan(
    const float* __restrict__ x,
    const float* __restrict__ mask)
{
    extern __shared__ float4 sm4[];
    float4* sq = sm4;                      // [TILE][SQS] packed {p,a,b,c}
    float4* os = sm4 + TILE * SQS;         // [TILE][OSS] output staging

    const int tid = threadIdx.x;
    const int blk = blockIdx.x;
    const int dir = blk & 3;               // interleave dirs -> mask L2 reuse
    const int bc  = blk >> 2;
    const int b   = bc >> 5;
    const int c   = bc & 31;
    const bool horiz = (dir < 2);
    const bool rev   = (dir & 1);

    const float* mb  = mask + (size_t)bc * PLANE;
    const float* g1b = x + (size_t)(b * 384 + (3 * dir + 0) * 32 + c) * PLANE;
    const float* g2b = x + (size_t)(b * 384 + (3 * dir + 1) * 32 + c) * PLANE;
    const float* g3b = x + (size_t)(b * 384 + (3 * dir + 2) * 32 + c) * PLANE;
    float* scr = g_scratch + (size_t)blk * PLANE;

    const int lane = tid & 31;
    const bool isScan = (tid < 32);        // warp 0 = scanner, owns whole k-line
    float h[8];
    #pragma unroll
    for (int e = 0; e < 8; ++e) h[e] = 0.f;

    for (int t = 0; t < HW / TILE; ++t) {
        const int base0 = rev ? (HW - TILE - TILE * t) : (TILE * t);

        // ---- cooperative load + normalize tile into sq (all 8 warps) ----
        if (horiz) {
            // tile = 256 rows(k) x 8 cols(c); float4 along c
            #pragma unroll
            for (int it = 0; it < 2; ++it) {
                int i  = tid + it * NT;            // 0..511
                int k  = i >> 1, c4 = i & 1;
                int g  = k * HW + base0 + c4 * 4;
                float4 M = *(const float4*)(mb  + g);
                float4 A = *(const float4*)(g1b + g);
                float4 B = *(const float4*)(g2b + g);
                float4 C = *(const float4*)(g3b + g);
                const float* Mp = (const float*)&M;
                const float* Ap = (const float*)&A;
                const float* Bp = (const float*)&B;
                const float* Cp = (const float*)&C;
                #pragma unroll
                for (int j = 0; j < 4; ++j) {
                    float G1 = Ap[j], G2 = Bp[j], G3 = Cp[j];
                    float s = fabsf(G1) + fabsf(G2) + fabsf(G3) + 1e-7f;
                    float r = (s >= 1.f) ? __fdividef(1.f, s) : 1.f;
                    float a = G1 * r, bb = G2 * r, cg = G3 * r;
                    float p = (1.f - a - bb - cg) * Mp[j];
                    int cc = c4 * 4 + j;
                    sq[cc * SQS + k + (k >> 3)] = make_float4(p, a, bb, cg);
                }
            }
        } else {
            // tile = 8 rows(t) x 256 cols(k); flat float4, fully coalesced
            #pragma unroll
            for (int it = 0; it < 2; ++it) {
                int i  = tid + it * NT;
                int tt = i >> 6, k4 = i & 63;
                int g  = (base0 + tt) * HW + k4 * 4;
                float4 M = *(const float4*)(mb  + g);
                float4 A = *(const float4*)(g1b + g);
                float4 B = *(const float4*)(g2b + g);
                float4 C = *(const float4*)(g3b + g);
                const float* Mp = (const float*)&M;
                const float* Ap = (const float*)&A;
                const float* Bp = (const float*)&B;
                const float* Cp = (const float*)&C;
                #pragma unroll
                for (int j = 0; j < 4; ++j) {
                    float G1 = Ap[j], G2 = Bp[j], G3 = Cp[j];
                    float s = fabsf(G1) + fabsf(G2) + fabsf(G3) + 1e-7f;
                    float r = (s >= 1.f) ? __fdividef(1.f, s) : 1.f;
                    float a = G1 * r, bb = G2 * r, cg = G3 * r;
                    float p = (1.f - a - bb - cg) * Mp[j];
                    int k = k4 * 4 + j;
                    sq[tt * SQS + k + (k >> 3)] = make_float4(p, a, bb, cg);
                }
            }
        }
        __syncthreads();

        // ---- warp-synchronous scan: 8 steps, ZERO barriers ----
        if (isScan) {
            #pragma unroll
            for (int st = 0; st < TILE; ++st) {
                int L = rev ? (TILE - 1 - st) : st;
                const float4* row = sq + L * SQS + lane * 9;   // k=8*lane+e -> 9*lane+e
                float hm = __shfl_up_sync(0xffffffffu, h[7], 1);   // h_prev(k-1)
                float hp = __shfl_down_sync(0xffffffffu, h[0], 1); // h_prev(k+1)
                if (lane == 0)  hm = 0.f;
                if (lane == 31) hp = 0.f;
                float hn[8];
                {
                    float4 q = row[0];
                    float v = fmaf(q.y, hm, q.x);
                    v = fmaf(q.z, h[0], v);
                    hn[0] = fmaf(q.w, h[1], v);
                }
                #pragma unroll
                for (int e = 1; e < 7; ++e) {
                    float4 q = row[e];
                    float v = fmaf(q.y, h[e - 1], q.x);
                    v = fmaf(q.z, h[e], v);
                    hn[e] = fmaf(q.w, h[e + 1], v);
                }
                {
                    float4 q = row[7];
                    float v = fmaf(q.y, h[6], q.x);
                    v = fmaf(q.z, h[7], v);
                    hn[7] = fmaf(q.w, hp, v);
                }
                #pragma unroll
                for (int e = 0; e < 8; ++e) h[e] = hn[e];
                float4* orow = os + L * OSS + lane * 2;
                orow[0] = make_float4(h[0], h[1], h[2], h[3]);
                orow[1] = make_float4(h[4], h[5], h[6], h[7]);
            }
        }
        __syncthreads();

        // ---- cooperative coalesced store of staging tile to scratch ----
        // horiz: rows are w (transposed layout); vert: rows are h (natural).
        #pragma unroll
        for (int it = 0; it < 2; ++it) {
            int f = tid + it * NT;                 // float4 index 0..511
            int L = f >> 6, k4 = f & 63;
            float4 v = os[L * OSS + k4];
            *(float4*)(scr + (base0 + L) * HW + k4 * 4) = v;
        }
        // No extra barrier: next tile's sq writes are fenced by the next
        // load-phase __syncthreads before the scanner touches sq/os again.
    }
}

// out(h,w) = max over 4 dirs. dirs 0,1 are transposed in scratch -> 32x32 smem transpose.
__global__ __launch_bounds__(256) void spn_max(float* __restrict__ out)
{
    __shared__ float t0[32][33], t1[32][33];
    const int bc   = blockIdx.x >> 6;
    const int tile = blockIdx.x & 63;
    const int h0 = (tile >> 3) * 32, w0 = (tile & 7) * 32;
    const int tx = threadIdx.x & 31, ty = threadIdx.x >> 5;  // 32 x 8
    const float* S = g_scratch + (size_t)bc * 4 * PLANE;

    #pragma unroll
    for (int r = 0; r < 4; ++r) {
        int wl = ty + 8 * r;
        int w  = w0 + wl;
        t0[wl][tx] = S[0 * PLANE + w * HW + h0 + tx];   // coalesced along h
        t1[wl][tx] = S[1 * PLANE + w * HW + h0 + tx];
    }
    __syncthreads();

    float* ob = out + (size_t)bc * PLANE;
    #pragma unroll
    for (int r = 0; r < 4; ++r) {
        int hl = ty + 8 * r;
        int g  = (h0 + hl) * HW + w0 + tx;
        float v = fmaxf(S[2 * PLANE + g], S[3 * PLANE + g]);
        v = fmaxf(v, fmaxf(t0[tx][hl], t1[tx][hl]));
        ob[g] = v;
    }
}

extern "C" void kernel_launch(void* const* d_in, const int* in_sizes, int n_in,
                              void* d_out, int out_size) {
    const float* x    = (const float*)d_in[0];
    const float* mask = (const float*)d_in[1];
    if (n_in >= 2 && in_sizes[0] < in_sizes[1]) {   // defensive: x is 12x mask
        x    = (const float*)d_in[1];
        mask = (const float*)d_in[0];
    }
    size_t smem = (size_t)(TILE * SQS + TILE * OSS) * sizeof(float4); // 45,440 B
    spn_scan<<<512, NT, smem>>>(x, mask);
    spn_max<<<128 * 64, 256>>>((float*)d_out);
}